// round 1
// baseline (speedup 1.0000x reference)
#include <cuda_runtime.h>
#include <math.h>

// ---------------- problem constants (fixed shapes) ----------------
#define Bb   112      // N*W = 2*56
#define Hh   56
#define F3   96       // OUT*3/2
#define OUTC 64
#define NHH  4
#define HB   2        // hash buckets
#define NP   224      // NHH*Hh
#define CH   25
#define KK   3
#define TP   75       // K*CHUNK
#define PADN 19
#define EPSN 5e-5f

// ---------------- scratch (device globals; no allocs) --------------
__device__ float g_qkv[Bb * 5376];    // (b, o*56+h) flat == (b, t*96+f) view
__device__ int   g_undo[Bb * NP];
__device__ float g_wb [Bb * 9600];    // (b, u*2400 + t*32 + f)
__device__ float g_vb [Bb * 19200];   // (b, u*4800 + t*64 + f)
__device__ float g_ret[Bb * 38400];   // (b, g*4800 + u*1200 + k*400 + i*16 + e)
__device__ float g_bs [Bb * 2400];    // (b, g*300 + u*75 + k*25 + i)
__device__ float g_k4 [Bb * 19200];   // (b, u*4800 + jj*64 + o)
__device__ float g_bsn[Bb * 300];     // (b, u*75 + jj)

// ---------------- K1: qkv = conv_w @ x, + BN ----------------
__global__ void k1_qkv(const float* __restrict__ x, const float* __restrict__ cw,
                       const float* __restrict__ gamma, const float* __restrict__ beta) {
    __shared__ float xs[64 * 56];
    __shared__ float ws[96 * 64];
    int n = blockIdx.x / 56, h = blockIdx.x % 56;
    for (int idx = threadIdx.x; idx < 64 * 56; idx += blockDim.x) {
        int c = idx / 56, w = idx % 56;
        xs[idx] = x[((n * 64 + c) * 56 + h) * 56 + w];
    }
    for (int idx = threadIdx.x; idx < 96 * 64; idx += blockDim.x) ws[idx] = cw[idx];
    __syncthreads();
    const float invbn = rsqrtf(1.0f + 1e-5f);
    for (int idx = threadIdx.x; idx < 96 * 56; idx += blockDim.x) {
        int o = idx / 56, w = idx % 56;
        float s = 0.f;
        #pragma unroll 16
        for (int c = 0; c < 64; c++) s += ws[o * 64 + c] * xs[c * 56 + w];
        s = s * invbn * gamma[o] + beta[o];
        g_qkv[(n * 56 + w) * 5376 + o * 56 + h] = s;
    }
}

// ---------------- K2: LSH codes + stable argsort + gather/pad ----------------
__global__ void k2_sort(const float* __restrict__ rot) {
    __shared__ int code[NP];
    __shared__ int srcr[NP];
    int b = blockIdx.x;
    int tid = threadIdx.x;
    if (tid < NP) {
        int u = tid / 56, t = tid % 56;
        const float* q = &g_qkv[b * 5376 + t * 96];
        float s = 0.f;
        #pragma unroll 8
        for (int f = 0; f < 32; f++) s += q[f] * rot[f * 4 + u];
        // argmax([r,-r]) -> 1 iff r<0 (ties -> 0), + u*hash_buckets
        code[tid] = (s < 0.f ? 1 : 0) + u * HB;
    }
    __syncthreads();
    if (tid < NP) {
        int c = code[tid];
        int r = 0;
        for (int j = 0; j < NP; j++) {
            int cj = code[j];
            r += (cj < c) || (cj == c && j < tid);   // stable rank
        }
        g_undo[b * NP + tid] = r;   // undo[j] = rank(j)
        srcr[r] = tid % 56;         // mod = indices % H
    }
    __syncthreads();
    // gather w_match -> padded w_b (B,4,75,32) flat
    for (int idx = tid; idx < 9600; idx += blockDim.x) {
        int u = idx / 2400, r = idx % 2400, t = r / 32, f = r % 32;
        int tt = (t < 56) ? t : t - PADN;
        int row = srcr[u * 56 + tt];
        g_wb[b * 9600 + idx] = g_qkv[b * 5376 + row * 96 + f];
    }
    // gather v_match -> padded v_b (B,4,75,64) flat
    for (int idx = tid; idx < 19200; idx += blockDim.x) {
        int u = idx / 4800, r = idx % 4800, t = r / 64, f = r % 64;
        int tt = (t < 56) ? t : t - PADN;
        int row = srcr[u * 56 + tt];
        g_vb[b * 19200 + idx] = g_qkv[b * 5376 + row * 96 + 32 + f];
    }
}

// adjacency roll mapping: j in [0,75) at chunk k -> source t in [0,75)
__device__ __forceinline__ int src_t(int j, int k) {
    if (j < 25) return k * 25 + j;
    if (j < 50) return ((k + 2) % 3) * 25 + (j - 25);
    return ((k + 1) % 3) * 25 + (j - 50);
}

// ---------------- K3: fused scores / cross-group l2norm / softmax / V ----------------
__global__ void k3_attn(const float* __restrict__ relative) {
    extern __shared__ float sm[];
    float* wr = sm;            // 2400: raw w_b rows   [g][t][4]
    float* wn = wr + 2400;     // 2400: l2norm'd rows  [g][t][4]
    float* va = wn + 2400;     // 4800: v_b rows       [g][t][8]
    float* we = va + 4800;     // 300:  w_emb padded   [t][4]
    float* ve = we + 300;      // 600:  v_emb padded   [t][8]
    float* ss = ve + 600;      // 15000: scores        [g][i][j]

    int blk = blockIdx.x;
    int b = blk / 12, r = blk % 12, u = r / 3, k = r % 3;
    int tid = threadIdx.x;

    const float* wbp = &g_wb[b * 9600 + u * 300];
    for (int idx = tid; idx < 2400; idx += 256)
        wr[idx] = wbp[(idx / 300) * 1200 + (idx % 300)];
    const float* vbp = &g_vb[b * 19200 + u * 600];
    for (int idx = tid; idx < 4800; idx += 256)
        va[idx] = vbp[(idx / 600) * 2400 + (idx % 600)];
    for (int t = tid; t < 75; t += 256) {
        int sr = (t < 56) ? t : t - PADN;
        #pragma unroll
        for (int e = 0; e < 4; e++) we[t * 4 + e] = relative[sr * 12 + e];
        #pragma unroll
        for (int e = 0; e < 8; e++) ve[t * 8 + e] = relative[sr * 12 + 4 + e];
    }
    __syncthreads();
    for (int rw = tid; rw < 600; rw += 256) {
        const float* p = &wr[rw * 4];
        float s = p[0]*p[0] + p[1]*p[1] + p[2]*p[2] + p[3]*p[3];
        float inv = 1.0f / fmaxf(sqrtf(s), EPSN);
        float* q = &wn[rw * 4];
        q[0] = p[0]*inv; q[1] = p[1]*inv; q[2] = p[2]*inv; q[3] = p[3]*inv;
    }
    __syncthreads();

    // phase 1: scores for all (i,j), cross-group l2norm over 16 channels
    for (int pos = tid; pos < 1875; pos += 256) {
        int i = pos / 75, j = pos % 75;
        int ti = k * 25 + i;
        int tj = src_t(j, k);
        const float* wej = &we[tj * 4];
        float rawv[8], embv[8];
        float sq = 0.f;
        #pragma unroll
        for (int g = 0; g < 8; g++) {
            const float* a = &wr[(g * 75 + ti) * 4];
            const float* m = &wn[(g * 75 + tj) * 4];
            float rv = a[0]*m[0] + a[1]*m[1] + a[2]*m[2] + a[3]*m[3];
            float ev = 0.1f * (a[0]*wej[0] + a[1]*wej[1] + a[2]*wej[2] + a[3]*wej[3]);
            rawv[g] = rv; embv[g] = ev;
            sq += rv * rv + ev * ev;
        }
        float inv = 1.0f / fmaxf(sqrtf(sq), EPSN);
        #pragma unroll
        for (int g = 0; g < 8; g++)
            ss[g * 1875 + i * 75 + j] = (rawv[g] + embv[g]) * inv;
    }
    __syncthreads();

    // phase 2: per (g,i) logsumexp + attention matvec
    if (tid < 200) {
        int g = tid / 25, i = tid % 25;
        const float* row = &ss[g * 1875 + i * 75];
        float m = -1e30f;
        for (int j = 0; j < 75; j++) m = fmaxf(m, row[j]);
        float acc[16];
        #pragma unroll
        for (int e = 0; e < 16; e++) acc[e] = 0.f;
        float sum = 0.f;
        for (int j = 0; j < 75; j++) {
            int tj = src_t(j, k);
            float e0 = expf(row[j] - m);
            sum += e0;
            const float* vp = &va[(g * 75 + tj) * 8];
            const float* ep = &ve[tj * 8];
            #pragma unroll
            for (int e = 0; e < 8; e++) {
                acc[e]     += e0 * vp[e];
                acc[8 + e] += e0 * ep[e];
            }
        }
        float invs = 1.0f / sum;
        g_bs[b * 2400 + g * 300 + u * 75 + k * 25 + i] = m + logf(sum);
        float* op = &g_ret[b * 38400 + g * 4800 + u * 1200 + k * 400 + i * 16];
        #pragma unroll
        for (int e = 0; e < 8; e++) {
            op[e]     = acc[e] * invs;           // F_GV2 = 1.0
            op[8 + e] = 0.1f * acc[8 + e] * invs; // F_GV1 = 0.1
        }
    }
}

// ---------------- K4: 128-channel l2norm (reinterpreted) + pair-sum; bs group-norm ----------------
__global__ void k4_norm() {
    __shared__ float nrm[300];
    int b = blockIdx.x;
    int tid = threadIdx.x;
    for (int m = tid; m < 300; m += blockDim.x) {
        float s = 0.f;
        const float* p = &g_ret[b * 38400 + m];
        #pragma unroll 8
        for (int c = 0; c < 128; c++) { float v = p[c * 300]; s += v * v; }
        nrm[m] = fmaxf(sqrtf(s), EPSN);
    }
    for (int m = tid; m < 300; m += blockDim.x) {
        const float* p = &g_bs[b * 2400 + m];
        float vals[8], s = 0.f;
        #pragma unroll
        for (int g = 0; g < 8; g++) { vals[g] = p[g * 300]; s += vals[g] * vals[g]; }
        float inv = 1.0f / fmaxf(sqrtf(s), EPSN);
        float t = 0.f;
        #pragma unroll
        for (int g = 0; g < 8; g++) t += vals[g] * inv;
        g_bsn[b * 300 + m] = t;
    }
    __syncthreads();
    for (int L2 = tid; L2 < 19200; L2 += blockDim.x) {
        int u = L2 / 4800, r = L2 % 4800, kk = r / 1600, r2 = r % 1600, i = r2 / 64, o = r2 % 64;
        int L0 = u * 9600 + kk * 3200 + i * 128 + o * 2;
        float x0 = g_ret[b * 38400 + L0];
        float x1 = g_ret[b * 38400 + L0 + 1];
        g_k4[b * 19200 + L2] = x0 / nrm[L0 % 300] + x1 / nrm[(L0 + 1) % 300];
    }
}

// ---------------- K5: unsort + hash softmax + output transpose ----------------
__global__ void k5_out(float* __restrict__ out) {
    __shared__ int   undo_s[NP];
    __shared__ float prob[4 * 56];
    __shared__ int   qoff[4 * 56];
    int b = blockIdx.x;
    int n = b / 56, w = b % 56;
    int tid = threadIdx.x;
    for (int j = tid; j < NP; j += blockDim.x) undo_s[j] = g_undo[b * NP + j];
    __syncthreads();
    if (tid < 56) {
        int h = tid;
        float bv[4];
        float mx = -1e30f;
        #pragma unroll
        for (int u = 0; u < 4; u++) {
            int q = undo_s[u * 56 + h];
            int qu = q / 56, qj = q % 56;
            bv[u] = g_bsn[b * 300 + qu * 75 + qj];
            qoff[u * 56 + h] = qu * 4800 + qj * 64;
            mx = fmaxf(mx, bv[u]);
        }
        float sm = 0.f;
        #pragma unroll
        for (int u = 0; u < 4; u++) { bv[u] = expf(bv[u] - mx); sm += bv[u]; }
        #pragma unroll
        for (int u = 0; u < 4; u++) prob[u * 56 + h] = bv[u] / sm;
    }
    __syncthreads();
    for (int idx = tid; idx < 56 * 64; idx += blockDim.x) {
        int h = idx / 64, o = idx % 64;
        float acc = 0.f;
        #pragma unroll
        for (int u = 0; u < 4; u++)
            acc += prob[u * 56 + h] * g_k4[b * 19200 + qoff[u * 56 + h] + o];
        out[((n * 64 + o) * 56 + h) * 56 + w] = acc;
    }
}

// ---------------- launch ----------------
extern "C" void kernel_launch(void* const* d_in, const int* in_sizes, int n_in,
                              void* d_out, int out_size) {
    const float* x        = (const float*)d_in[0];
    const float* cw       = (const float*)d_in[1];
    const float* gamma    = (const float*)d_in[2];
    const float* beta     = (const float*)d_in[3];
    const float* relative = (const float*)d_in[4];
    const float* rotations= (const float*)d_in[5];
    float* out = (float*)d_out;

    cudaFuncSetAttribute(k3_attn, cudaFuncAttributeMaxDynamicSharedMemorySize, 25500 * 4);

    k1_qkv <<<112, 256>>>(x, cw, gamma, beta);
    k2_sort<<<112, 256>>>(rotations);
    k3_attn<<<Bb * 12, 256, 25500 * 4>>>(relative);
    k4_norm<<<112, 512>>>();
    k5_out <<<112, 256>>>(out);
}